// round 1
// baseline (speedup 1.0000x reference)
#include <cuda_runtime.h>
#include <cuda_bf16.h>
#include <cstdint>

// Problem constants
#define B_    32
#define U_    4096
#define D_    512      // D_DEC == D_ENC
#define H_    4
#define HD_   128      // head dim
#define CK_   31       // conv taps
#define CF_   32       // conv filters
#define AU_   512      // ATT_UNITS
#define UCHUNK 256
#define NCHUNK (U_ / UCHUNK)   // 16

// ---------------- scratch (device globals; no allocations allowed) ----------
__device__ float g_KEFF[CK_ * H_];                 // effective conv kernel (31x4)
__device__ float g_V[B_ * H_ * D_];                // v[b,h,e] = phi . Wpsi
__device__ float g_E[(size_t)B_ * H_ * U_];        // energies
__device__ float g_ATTN[(size_t)B_ * H_ * U_];     // normalized attention
__device__ float g_CTX[B_ * H_ * D_];              // context accumulators

// ---------------- kernel: effective conv kernel  Keff[k,h] ------------------
__global__ void keff_kernel(const float* __restrict__ ck,    // (31,1,32)
                            const float* __restrict__ Wloc)  // (32,4)
{
    int i = threadIdx.x;
    if (i < CK_ * H_) {
        int k = i >> 2, h = i & 3;
        float s = 0.f;
        #pragma unroll
        for (int f = 0; f < CF_; f++)
            s += ck[k * CF_ + f] * Wloc[f * H_ + h];
        g_KEFF[i] = s;
    }
}

// ---------------- kernel: zero context accumulator ---------------------------
__global__ void zero_ctx_kernel()
{
    int i = blockIdx.x * blockDim.x + threadIdx.x;
    if (i < B_ * H_ * D_) g_CTX[i] = 0.f;
}

// ---------------- kernel: phi = dec@Wphi + bphi ;  v = phi . Wpsi -----------
// grid = B*H blocks of 128 threads
__global__ void phiv_kernel(const float* __restrict__ dec,
                            const float* __restrict__ Wphi,  // (H, D, HD)
                            const float* __restrict__ bphi,  // (H, HD)
                            const float* __restrict__ Wpsi)  // (H, D, HD)
{
    int bh = blockIdx.x;
    int b = bh >> 2, h = bh & 3;
    __shared__ float dec_sm[D_];
    __shared__ float phi_sm[HD_];
    int tid = threadIdx.x;           // 128

    for (int i = tid; i < D_; i += 128) dec_sm[i] = dec[(size_t)b * D_ + i];
    __syncthreads();

    // phi[k], k = tid
    float acc = bphi[h * HD_ + tid];
    const float* w = Wphi + (size_t)h * D_ * HD_ + tid;
    #pragma unroll 8
    for (int d = 0; d < D_; d++)
        acc += dec_sm[d] * w[(size_t)d * HD_];
    phi_sm[tid] = acc;
    __syncthreads();

    // v[e] = sum_k phi[k] * Wpsi[h, e, k]
    for (int e = tid; e < D_; e += 128) {
        const float4* wp = reinterpret_cast<const float4*>(
            Wpsi + ((size_t)h * D_ + e) * HD_);
        float vv = 0.f;
        #pragma unroll 8
        for (int k4 = 0; k4 < HD_ / 4; k4++) {
            float4 ww = wp[k4];
            vv += ww.x * phi_sm[4 * k4 + 0] + ww.y * phi_sm[4 * k4 + 1]
                + ww.z * phi_sm[4 * k4 + 2] + ww.w * phi_sm[4 * k4 + 3];
        }
        g_V[(size_t)bh * D_ + e] = vv;
    }
}

// ---------------- kernel: energies  E[b,h,u] = enc[b,u,:].v[b,h,:] + loc ----
// grid (NCHUNK, B), block 256 (8 warps); one warp per u
__global__ void energy_kernel(const float* __restrict__ enc,
                              const float* __restrict__ prev)
{
    int b = blockIdx.y;
    int u0 = blockIdx.x * UCHUNK;
    __shared__ float prev_sm[UCHUNK + CK_ - 1];   // 286, halo of 15 each side
    __shared__ float keff_sm[CK_ * H_];
    int tid = threadIdx.x;

    for (int i = tid; i < UCHUNK + CK_ - 1; i += 256) {
        int gu = u0 + i - 15;
        prev_sm[i] = (gu >= 0 && gu < U_) ? prev[(size_t)b * U_ + gu] : 0.f;
    }
    if (tid < CK_ * H_) keff_sm[tid] = g_KEFF[tid];
    __syncthreads();

    int warp = tid >> 5, lane = tid & 31;

    // v for all 4 heads in registers: lane owns float4 chunks lane+32*i
    float4 vr[H_][4];
    #pragma unroll
    for (int h = 0; h < H_; h++) {
        const float4* vp = reinterpret_cast<const float4*>(
            g_V + (size_t)(b * H_ + h) * D_);
        #pragma unroll
        for (int i = 0; i < 4; i++) vr[h][i] = vp[lane + 32 * i];
    }

    for (int uu = warp; uu < UCHUNK; uu += 8) {
        int u = u0 + uu;
        const float4* row = reinterpret_cast<const float4*>(
            enc + ((size_t)b * U_ + u) * D_);
        float a0 = 0.f, a1 = 0.f, a2 = 0.f, a3 = 0.f;
        #pragma unroll
        for (int i = 0; i < 4; i++) {
            float4 x = row[lane + 32 * i];
            a0 += x.x*vr[0][i].x + x.y*vr[0][i].y + x.z*vr[0][i].z + x.w*vr[0][i].w;
            a1 += x.x*vr[1][i].x + x.y*vr[1][i].y + x.z*vr[1][i].z + x.w*vr[1][i].w;
            a2 += x.x*vr[2][i].x + x.y*vr[2][i].y + x.z*vr[2][i].z + x.w*vr[2][i].w;
            a3 += x.x*vr[3][i].x + x.y*vr[3][i].y + x.z*vr[3][i].z + x.w*vr[3][i].w;
        }
        #pragma unroll
        for (int off = 16; off; off >>= 1) {
            a0 += __shfl_xor_sync(0xffffffffu, a0, off);
            a1 += __shfl_xor_sync(0xffffffffu, a1, off);
            a2 += __shfl_xor_sync(0xffffffffu, a2, off);
            a3 += __shfl_xor_sync(0xffffffffu, a3, off);
        }
        if (lane < H_) {
            float a = (lane == 0) ? a0 : (lane == 1) ? a1 : (lane == 2) ? a2 : a3;
            float lb = 0.f;
            #pragma unroll
            for (int k = 0; k < CK_; k++)
                lb += prev_sm[uu + k] * keff_sm[k * H_ + lane];
            g_E[((size_t)(b * H_ + lane)) * U_ + u] = a + lb;
        }
    }
}

// ---------------- kernel: softmax per (b,h) row over U -----------------------
// grid B*H, block 256
__global__ void softmax_kernel()
{
    int row = blockIdx.x;
    int tid = threadIdx.x;
    int warp = tid >> 5, lane = tid & 31;
    __shared__ float es[U_];
    __shared__ float red[8];

    const float* e = g_E + (size_t)row * U_;
    float lm = -1e30f;
    for (int i = tid; i < U_; i += 256) {
        float v = e[i];
        es[i] = v;
        lm = fmaxf(lm, v);
    }
    #pragma unroll
    for (int off = 16; off; off >>= 1) lm = fmaxf(lm, __shfl_xor_sync(~0u, lm, off));
    if (lane == 0) red[warp] = lm;
    __syncthreads();
    if (warp == 0) {
        float v = (lane < 8) ? red[lane] : -1e30f;
        #pragma unroll
        for (int off = 4; off; off >>= 1) v = fmaxf(v, __shfl_xor_sync(~0u, v, off));
        if (lane == 0) red[0] = v;
    }
    __syncthreads();
    float m = red[0];
    __syncthreads();

    float ls = 0.f;
    for (int i = tid; i < U_; i += 256) {
        float t = __expf(es[i] - m);
        es[i] = t;
        ls += t;
    }
    #pragma unroll
    for (int off = 16; off; off >>= 1) ls += __shfl_xor_sync(~0u, ls, off);
    if (lane == 0) red[warp] = ls;
    __syncthreads();
    if (warp == 0) {
        float v = (lane < 8) ? red[lane] : 0.f;
        #pragma unroll
        for (int off = 4; off; off >>= 1) v += __shfl_xor_sync(~0u, v, off);
        if (lane == 0) red[0] = v;
    }
    __syncthreads();
    float inv = 1.f / red[0];

    float* a = g_ATTN + (size_t)row * U_;
    for (int i = tid; i < U_; i += 256) a[i] = es[i] * inv;
}

// ---------------- kernel: attention_weights = mean over heads ----------------
// grid B, block 256; writes to d_out offset B*AU
__global__ void aw_kernel(float* __restrict__ out)
{
    int b = blockIdx.x;
    const float* a0 = g_ATTN + (size_t)(b * H_ + 0) * U_;
    const float* a1 = g_ATTN + (size_t)(b * H_ + 1) * U_;
    const float* a2 = g_ATTN + (size_t)(b * H_ + 2) * U_;
    const float* a3 = g_ATTN + (size_t)(b * H_ + 3) * U_;
    float* o = out + (size_t)B_ * AU_ + (size_t)b * U_;
    for (int u = threadIdx.x; u < U_; u += 256)
        o[u] = 0.25f * (a0[u] + a1[u] + a2[u] + a3[u]);
}

// ---------------- kernel: context partials  ctx[b,h,:] += attn . enc ---------
// grid (NCHUNK, B), block 256; thread owns 2 consecutive e-columns
__global__ void context_kernel(const float* __restrict__ enc)
{
    int b = blockIdx.y;
    int u0 = blockIdx.x * UCHUNK;
    int tid = threadIdx.x;
    __shared__ float a_sm[H_][UCHUNK];

    for (int i = tid; i < H_ * UCHUNK; i += 256) {
        int h = i >> 8, uu = i & (UCHUNK - 1);
        a_sm[h][uu] = g_ATTN[((size_t)(b * H_ + h)) * U_ + u0 + uu];
    }
    __syncthreads();

    float2 acc[H_];
    #pragma unroll
    for (int h = 0; h < H_; h++) { acc[h].x = 0.f; acc[h].y = 0.f; }

    for (int uu = 0; uu < UCHUNK; uu++) {
        float2 x = reinterpret_cast<const float2*>(
            enc + ((size_t)b * U_ + u0 + uu) * D_)[tid];
        #pragma unroll
        for (int h = 0; h < H_; h++) {
            float w = a_sm[h][uu];
            acc[h].x += w * x.x;
            acc[h].y += w * x.y;
        }
    }
    #pragma unroll
    for (int h = 0; h < H_; h++) {
        float* c = g_CTX + (size_t)(b * H_ + h) * D_ + 2 * tid;
        atomicAdd(c + 0, acc[h].x);
        atomicAdd(c + 1, acc[h].y);
    }
}

// ---------------- kernel: context_vector = ctx_flat @ Wout + bout ------------
// grid B, block 512
__global__ void out_kernel(const float* __restrict__ Wout,  // (H*D, AU)
                           const float* __restrict__ bout,  // (AU,)
                           float* __restrict__ out)
{
    int b = blockIdx.x;
    int tid = threadIdx.x;   // 512 = one output column each
    __shared__ float c_sm[H_ * D_];
    for (int i = tid; i < H_ * D_; i += 512)
        c_sm[i] = g_CTX[(size_t)b * H_ * D_ + i];
    __syncthreads();

    float acc = bout[tid];
    #pragma unroll 8
    for (int i = 0; i < H_ * D_; i++)
        acc += c_sm[i] * Wout[(size_t)i * AU_ + tid];
    out[(size_t)b * AU_ + tid] = acc;
}

// ---------------------------------------------------------------------------
extern "C" void kernel_launch(void* const* d_in, const int* in_sizes, int n_in,
                              void* d_out, int out_size)
{
    const float* dec   = (const float*)d_in[0];   // (B, 512)
    const float* enc   = (const float*)d_in[1];   // (B, U, 512)
    const float* prev  = (const float*)d_in[2];   // (B, U)
    const float* Wphi  = (const float*)d_in[3];   // (4, 512, 128)
    const float* bphi  = (const float*)d_in[4];   // (4, 128)
    const float* Wpsi  = (const float*)d_in[5];   // (4, 512, 128)
    // d_in[6] = bpsi : per-(b,h) constant along u -> softmax invariant, unused
    const float* ck    = (const float*)d_in[7];   // (31, 1, 32)
    const float* Wloc  = (const float*)d_in[8];   // (32, 4)
    const float* Wout  = (const float*)d_in[9];   // (2048, 512)
    const float* bout  = (const float*)d_in[10];  // (512,)
    float* out = (float*)d_out;

    zero_ctx_kernel<<<(B_ * H_ * D_ + 255) / 256, 256>>>();
    keff_kernel<<<1, 128>>>(ck, Wloc);
    phiv_kernel<<<B_ * H_, 128>>>(dec, Wphi, bphi, Wpsi);
    energy_kernel<<<dim3(NCHUNK, B_), 256>>>(enc, prev);
    softmax_kernel<<<B_ * H_, 256>>>();
    aw_kernel<<<B_, 256>>>(out);
    context_kernel<<<dim3(NCHUNK, B_), 256>>>(enc);
    out_kernel<<<B_, 512>>>(Wout, bout, out);
}

// round 2
// speedup vs baseline: 1.5544x; 1.5544x over previous
#include <cuda_runtime.h>
#include <cuda_bf16.h>
#include <cstdint>

// Problem constants
#define B_    32
#define U_    4096
#define D_    512
#define H_    4
#define HD_   128
#define CK_   31
#define CF_   32
#define AU_   512

// Fused kernel tiling
#define UC    128            // u rows per CTA
#define NC    (U_ / UC)      // 32 chunks
#define ST    32             // subtile rows per pipeline stage
#define NSUB  (UC / ST)      // 4
#define TILE_BYTES (ST * D_ * 4)   // 65536

// ---------------- scratch (device globals) ----------------------------------
__device__ float g_KEFF[CK_ * H_];
__device__ float g_V[B_ * H_ * D_];
__device__ float g_E[(size_t)B_ * H_ * U_];                 // raw energies
__device__ float g_CTXP[(size_t)B_ * NC * H_ * D_];         // per-chunk ctx partials
__device__ float g_MSP[B_ * NC * H_ * 2];                   // per-chunk (m, s)
__device__ float g_CTX[B_ * H_ * D_];                       // normalized context
__device__ float g_MS[B_ * H_ * 2];                         // global (m, S)
__device__ float g_OUTP[B_ * 4 * AU_];                      // out GEMM partials

// ---------------- PTX helpers -----------------------------------------------
__device__ __forceinline__ uint32_t smem_u32(const void* p) {
    uint32_t a;
    asm("{ .reg .u64 t; cvta.to.shared.u64 t, %1; cvt.u32.u64 %0, t; }"
        : "=r"(a) : "l"(p));
    return a;
}
__device__ __forceinline__ void mbar_init(uint32_t mbar, uint32_t cnt) {
    asm volatile("mbarrier.init.shared.b64 [%0], %1;" :: "r"(mbar), "r"(cnt) : "memory");
}
__device__ __forceinline__ void mbar_expect_tx(uint32_t mbar, uint32_t bytes) {
    asm volatile("mbarrier.arrive.expect_tx.shared.b64 _, [%0], %1;"
                 :: "r"(mbar), "r"(bytes) : "memory");
}
__device__ __forceinline__ void mbar_wait(uint32_t mbar, uint32_t parity) {
    uint32_t done;
    asm volatile(
        "{\n\t.reg .pred p;\n\t"
        "mbarrier.try_wait.parity.acquire.cta.shared::cta.b64 p, [%1], %2;\n\t"
        "selp.b32 %0, 1, 0, p;\n\t}"
        : "=r"(done) : "r"(mbar), "r"(parity) : "memory");
    if (!done) {
        asm volatile(
            "{\n\t.reg .pred P1;\n\t"
            "W_%=:\n\t"
            "mbarrier.try_wait.parity.acquire.cta.shared::cta.b64 P1, [%0], %1, 0x989680;\n\t"
            "@P1 bra.uni D_%=;\n\t"
            "bra.uni W_%=;\n\t"
            "D_%=:\n\t}"
            :: "r"(mbar), "r"(parity) : "memory");
    }
}
__device__ __forceinline__ void bulk_g2s(uint32_t dst, const void* src,
                                         uint32_t bytes, uint32_t mbar) {
    asm volatile(
        "cp.async.bulk.shared::cta.global.mbarrier::complete_tx::bytes "
        "[%0], [%1], %2, [%3];"
        :: "r"(dst), "l"(src), "r"(bytes), "r"(mbar) : "memory");
}
__device__ __forceinline__ void fence_proxy_async_sc() {
    asm volatile("fence.proxy.async.shared::cta;" ::: "memory");
}

// ---------------- kernel: effective conv kernel -----------------------------
__global__ void keff_kernel(const float* __restrict__ ck,
                            const float* __restrict__ Wloc)
{
    int i = threadIdx.x;
    if (i < CK_ * H_) {
        int k = i >> 2, h = i & 3;
        float s = 0.f;
        #pragma unroll
        for (int f = 0; f < CF_; f++) s += ck[k * CF_ + f] * Wloc[f * H_ + h];
        g_KEFF[i] = s;
    }
}

// ---------------- kernel: phi & v -------------------------------------------
__global__ void phiv_kernel(const float* __restrict__ dec,
                            const float* __restrict__ Wphi,
                            const float* __restrict__ bphi,
                            const float* __restrict__ Wpsi)
{
    int bh = blockIdx.x;
    int b = bh >> 2, h = bh & 3;
    __shared__ float dec_sm[D_];
    __shared__ float phi_sm[HD_];
    int tid = threadIdx.x;   // 128

    for (int i = tid; i < D_; i += 128) dec_sm[i] = dec[(size_t)b * D_ + i];
    __syncthreads();

    float acc = bphi[h * HD_ + tid];
    const float* w = Wphi + (size_t)h * D_ * HD_ + tid;
    #pragma unroll 8
    for (int d = 0; d < D_; d++) acc += dec_sm[d] * w[(size_t)d * HD_];
    phi_sm[tid] = acc;
    __syncthreads();

    for (int e = tid; e < D_; e += 128) {
        const float4* wp = reinterpret_cast<const float4*>(
            Wpsi + ((size_t)h * D_ + e) * HD_);
        float vv = 0.f;
        #pragma unroll 8
        for (int k4 = 0; k4 < HD_ / 4; k4++) {
            float4 ww = wp[k4];
            vv += ww.x * phi_sm[4 * k4 + 0] + ww.y * phi_sm[4 * k4 + 1]
                + ww.z * phi_sm[4 * k4 + 2] + ww.w * phi_sm[4 * k4 + 3];
        }
        g_V[(size_t)bh * D_ + e] = vv;
    }
}

// ---------------- fused: energy + online softmax + context partials ---------
// grid (NC, B), block 256. Dynamic smem.
// smem float layout:
//   [0)        enc0    : ST*D   = 16384
//   [16384)    enc1    : 16384
//   [32768)    prevs   : UC+30  = 158
//   [32926)    keffs   : 124
//   [33050)    e_sm    : H*ST   = 128
//   [33178)    p_sm    : H*ST   = 128
//   [33306)    fac_sm  : 4
//   [33310)    m_sm    : 4
//   [33314)    s_sm    : 4
//   [33320)    mbar[2] : 4 floats (2x u64)
#define SMEM_FUSED_BYTES ((33324) * 4)

__global__ void __launch_bounds__(256, 1)
fused_kernel(const float* __restrict__ enc,
             const float* __restrict__ prev)
{
    extern __shared__ float smem[];
    float* enc_sm[2] = { smem, smem + ST * D_ };
    float* prevs  = smem + 32768;
    float* keffs  = prevs + (UC + 30);
    float* e_sm   = keffs + CK_ * H_;
    float* p_sm   = e_sm + H_ * ST;
    float* fac_sm = p_sm + H_ * ST;
    float* m_sm   = fac_sm + H_;
    float* s_sm   = m_sm + H_;
    uint32_t bar0 = smem_u32(smem + 33320);
    uint32_t bar1 = bar0 + 8;

    int tid  = threadIdx.x;
    int warp = tid >> 5, lane = tid & 31;
    int b  = blockIdx.y;
    int u0 = blockIdx.x * UC;
    const float* enc_base = enc + ((size_t)b * U_ + u0) * D_;

    if (tid == 0) {
        mbar_init(bar0, 1);
        mbar_init(bar1, 1);
        fence_proxy_async_sc();
    }
    if (tid < H_) { m_sm[tid] = -1e30f; s_sm[tid] = 0.f; }
    __syncthreads();

    if (tid == 0) {
        mbar_expect_tx(bar0, TILE_BYTES);
        bulk_g2s(smem_u32(enc_sm[0]), enc_base, TILE_BYTES, bar0);
        mbar_expect_tx(bar1, TILE_BYTES);
        bulk_g2s(smem_u32(enc_sm[1]), enc_base + ST * D_, TILE_BYTES, bar1);
    }

    // stage prev halo + keff + v while copies fly
    for (int i = tid; i < UC + 30; i += 256) {
        int gu = u0 + i - 15;
        prevs[i] = (gu >= 0 && gu < U_) ? prev[(size_t)b * U_ + gu] : 0.f;
    }
    if (tid < CK_ * H_) keffs[tid] = g_KEFF[tid];

    float4 vr[H_][4];
    #pragma unroll
    for (int h = 0; h < H_; h++) {
        const float4* vp = reinterpret_cast<const float4*>(
            g_V + (size_t)(b * H_ + h) * D_);
        #pragma unroll
        for (int i = 0; i < 4; i++) vr[h][i] = vp[lane + 32 * i];
    }

    float2 acc[H_];
    #pragma unroll
    for (int h = 0; h < H_; h++) { acc[h].x = 0.f; acc[h].y = 0.f; }

    __syncthreads();  // prevs/keffs ready

    for (int s = 0; s < NSUB; s++) {
        int buf = s & 1;
        mbar_wait(buf ? bar1 : bar0, (s >> 1) & 1);

        // ---- energy: warp handles rows warp*4 .. warp*4+3 ----
        const float* tile = enc_sm[buf];
        #pragma unroll
        for (int rr = 0; rr < 4; rr++) {
            int r = warp * 4 + rr;
            const float4* row = reinterpret_cast<const float4*>(tile + r * D_);
            float a0 = 0.f, a1 = 0.f, a2 = 0.f, a3 = 0.f;
            #pragma unroll
            for (int i = 0; i < 4; i++) {
                float4 x = row[lane + 32 * i];
                a0 += x.x*vr[0][i].x + x.y*vr[0][i].y + x.z*vr[0][i].z + x.w*vr[0][i].w;
                a1 += x.x*vr[1][i].x + x.y*vr[1][i].y + x.z*vr[1][i].z + x.w*vr[1][i].w;
                a2 += x.x*vr[2][i].x + x.y*vr[2][i].y + x.z*vr[2][i].z + x.w*vr[2][i].w;
                a3 += x.x*vr[3][i].x + x.y*vr[3][i].y + x.z*vr[3][i].z + x.w*vr[3][i].w;
            }
            #pragma unroll
            for (int off = 16; off; off >>= 1) {
                a0 += __shfl_xor_sync(0xffffffffu, a0, off);
                a1 += __shfl_xor_sync(0xffffffffu, a1, off);
                a2 += __shfl_xor_sync(0xffffffffu, a2, off);
                a3 += __shfl_xor_sync(0xffffffffu, a3, off);
            }
            if (lane < H_) {
                float a = (lane == 0) ? a0 : (lane == 1) ? a1 : (lane == 2) ? a2 : a3;
                int uu = s * ST + r;
                float lb = 0.f;
                #pragma unroll
                for (int k = 0; k < CK_; k++)
                    lb += prevs[uu + k] * keffs[k * H_ + lane];
                float e = a + lb;
                e_sm[lane * ST + r] = e;
                g_E[((size_t)(b * H_ + lane)) * U_ + u0 + uu] = e;
            }
        }
        __syncthreads();

        // ---- online softmax update (one warp per head) ----
        if (warp < H_) {
            int h = warp;
            float e = e_sm[h * ST + lane];
            float mloc = e;
            #pragma unroll
            for (int off = 16; off; off >>= 1)
                mloc = fmaxf(mloc, __shfl_xor_sync(0xffffffffu, mloc, off));
            float mold = m_sm[h];
            float mnew = fmaxf(mold, mloc);
            float p = __expf(e - mnew);
            float ssub = p;
            #pragma unroll
            for (int off = 16; off; off >>= 1)
                ssub += __shfl_xor_sync(0xffffffffu, ssub, off);
            p_sm[h * ST + lane] = p;
            if (lane == 0) {
                float fac = __expf(mold - mnew);
                fac_sm[h] = fac;
                s_sm[h] = s_sm[h] * fac + ssub;
                m_sm[h] = mnew;
            }
        }
        __syncthreads();

        // ---- context accumulation (thread owns 2 columns) ----
        {
            float f0 = fac_sm[0], f1 = fac_sm[1], f2 = fac_sm[2], f3 = fac_sm[3];
            acc[0].x *= f0; acc[0].y *= f0;
            acc[1].x *= f1; acc[1].y *= f1;
            acc[2].x *= f2; acc[2].y *= f2;
            acc[3].x *= f3; acc[3].y *= f3;
            const float* tp = tile + 2 * tid;
            #pragma unroll 4
            for (int r = 0; r < ST; r++) {
                float2 x = *reinterpret_cast<const float2*>(tp + r * D_);
                float p0 = p_sm[0 * ST + r], p1 = p_sm[1 * ST + r];
                float p2 = p_sm[2 * ST + r], p3 = p_sm[3 * ST + r];
                acc[0].x += p0 * x.x; acc[0].y += p0 * x.y;
                acc[1].x += p1 * x.x; acc[1].y += p1 * x.y;
                acc[2].x += p2 * x.x; acc[2].y += p2 * x.y;
                acc[3].x += p3 * x.x; acc[3].y += p3 * x.y;
            }
        }
        __syncthreads();

        // ---- prefetch subtile s+2 into this buffer ----
        if (tid == 0 && s + 2 < NSUB) {
            uint32_t bar = buf ? bar1 : bar0;
            mbar_expect_tx(bar, TILE_BYTES);
            bulk_g2s(smem_u32(enc_sm[buf]), enc_base + (s + 2) * ST * D_,
                     TILE_BYTES, bar);
        }
    }

    // ---- write partials ----
    size_t chunk = (size_t)b * NC + blockIdx.x;
    #pragma unroll
    for (int h = 0; h < H_; h++) {
        float* cp = g_CTXP + (chunk * H_ + h) * D_ + 2 * tid;
        cp[0] = acc[h].x; cp[1] = acc[h].y;
    }
    if (tid < H_) {
        g_MSP[(chunk * H_ + tid) * 2 + 0] = m_sm[tid];
        g_MSP[(chunk * H_ + tid) * 2 + 1] = s_sm[tid];
    }
}

// ---------------- combine partials per (b,h) --------------------------------
// grid (H, B), block 256
__global__ void combine_kernel()
{
    int h = blockIdx.x, b = blockIdx.y;
    int tid = threadIdx.x, lane = tid & 31;
    __shared__ float w_sm[NC];
    __shared__ float invS_sm;

    if (tid < 32) {
        float mc = g_MSP[(((size_t)b * NC + lane) * H_ + h) * 2 + 0];
        float sc = g_MSP[(((size_t)b * NC + lane) * H_ + h) * 2 + 1];
        float m = mc;
        #pragma unroll
        for (int off = 16; off; off >>= 1)
            m = fmaxf(m, __shfl_xor_sync(0xffffffffu, m, off));
        float w = __expf(mc - m);
        float sw = sc * w;
        #pragma unroll
        for (int off = 16; off; off >>= 1)
            sw += __shfl_xor_sync(0xffffffffu, sw, off);
        w_sm[lane] = w;
        if (lane == 0) {
            invS_sm = 1.f / sw;
            g_MS[(b * H_ + h) * 2 + 0] = m;
            g_MS[(b * H_ + h) * 2 + 1] = sw;
        }
    }
    __syncthreads();
    float invS = invS_sm;

    // each thread: 2 columns
    float a0 = 0.f, a1 = 0.f;
    #pragma unroll 4
    for (int c = 0; c < NC; c++) {
        const float* cp = g_CTXP + (((size_t)b * NC + c) * H_ + h) * D_ + 2 * tid;
        float w = w_sm[c];
        a0 += w * cp[0];
        a1 += w * cp[1];
    }
    float* o = g_CTX + (size_t)(b * H_ + h) * D_ + 2 * tid;
    o[0] = a0 * invS;
    o[1] = a1 * invS;
}

// ---------------- attention weights (mean over heads) -----------------------
// grid B, block 256; writes d_out offset B*AU
__global__ void aw_kernel(float* __restrict__ out)
{
    int b = blockIdx.x;
    float m0 = g_MS[(b*H_+0)*2], i0 = 1.f / g_MS[(b*H_+0)*2+1];
    float m1 = g_MS[(b*H_+1)*2], i1 = 1.f / g_MS[(b*H_+1)*2+1];
    float m2 = g_MS[(b*H_+2)*2], i2 = 1.f / g_MS[(b*H_+2)*2+1];
    float m3 = g_MS[(b*H_+3)*2], i3 = 1.f / g_MS[(b*H_+3)*2+1];
    const float* e0 = g_E + (size_t)(b*H_+0) * U_;
    const float* e1 = g_E + (size_t)(b*H_+1) * U_;
    const float* e2 = g_E + (size_t)(b*H_+2) * U_;
    const float* e3 = g_E + (size_t)(b*H_+3) * U_;
    float* o = out + (size_t)B_ * AU_ + (size_t)b * U_;
    for (int u = threadIdx.x; u < U_; u += 256) {
        float v = __expf(e0[u]-m0)*i0 + __expf(e1[u]-m1)*i1
                + __expf(e2[u]-m2)*i2 + __expf(e3[u]-m3)*i3;
        o[u] = 0.25f * v;
    }
}

// ---------------- out GEMM partials: grid (4, B), block 512 -----------------
__global__ void outp_kernel(const float* __restrict__ Wout)
{
    int s = blockIdx.x, b = blockIdx.y;
    int tid = threadIdx.x;
    __shared__ float c_sm[AU_];
    c_sm[tid] = g_CTX[(size_t)b * H_ * D_ + s * AU_ + tid];
    __syncthreads();

    const float* wbase = Wout + (size_t)s * AU_ * AU_ + tid;
    float acc = 0.f;
    #pragma unroll 8
    for (int i = 0; i < AU_; i++)
        acc += c_sm[i] * wbase[(size_t)i * AU_];
    g_OUTP[(b * 4 + s) * AU_ + tid] = acc;
}

// ---------------- out final: grid B, block 512 ------------------------------
__global__ void outf_kernel(const float* __restrict__ bout,
                            float* __restrict__ out)
{
    int b = blockIdx.x, t = threadIdx.x;
    float v = bout[t]
            + g_OUTP[(b*4+0)*AU_ + t] + g_OUTP[(b*4+1)*AU_ + t]
            + g_OUTP[(b*4+2)*AU_ + t] + g_OUTP[(b*4+3)*AU_ + t];
    out[(size_t)b * AU_ + t] = v;
}

// ---------------------------------------------------------------------------
extern "C" void kernel_launch(void* const* d_in, const int* in_sizes, int n_in,
                              void* d_out, int out_size)
{
    const float* dec   = (const float*)d_in[0];
    const float* enc   = (const float*)d_in[1];
    const float* prev  = (const float*)d_in[2];
    const float* Wphi  = (const float*)d_in[3];
    const float* bphi  = (const float*)d_in[4];
    const float* Wpsi  = (const float*)d_in[5];
    // d_in[6] = bpsi: constant along u per (b,h) -> softmax-invariant, unused
    const float* ck    = (const float*)d_in[7];
    const float* Wloc  = (const float*)d_in[8];
    const float* Wout  = (const float*)d_in[9];
    const float* bout  = (const float*)d_in[10];
    float* out = (float*)d_out;

    cudaFuncSetAttribute(fused_kernel,
                         cudaFuncAttributeMaxDynamicSharedMemorySize,
                         SMEM_FUSED_BYTES);

    keff_kernel<<<1, 128>>>(ck, Wloc);
    phiv_kernel<<<B_ * H_, 128>>>(dec, Wphi, bphi, Wpsi);
    fused_kernel<<<dim3(NC, B_), 256, SMEM_FUSED_BYTES>>>(enc, prev);
    combine_kernel<<<dim3(H_, B_), 256>>>();
    aw_kernel<<<B_, 256>>>(out);
    outp_kernel<<<dim3(4, B_), 512>>>(Wout);
    outf_kernel<<<B_, 512>>>(bout, out);
}